// round 2
// baseline (speedup 1.0000x reference)
#include <cuda_runtime.h>
#include <math.h>

#define NN    5000
#define EE    50000
#define LL    9
#define CC    128
#define NHEAD 8
#define NLROWS (NN*LL)   // 45000

// ------------------------- device scratch (static, no allocs) -------------------------
__device__ float g_Y[NLROWS*256];       // [node*9, 256]: cols 0..127 = x@Wm_top, 128..255 = x@Wm_bot
__device__ float g_WmsgC[128*256];      // packed [k][c] : c<128 -> W_msg[k][c], else W_msg[128+k][c-128]
__device__ float g_bz[100*128];
__device__ float g_cz[100*128];
__device__ float g_u[8*128];            // u[h][c] = sum_vc W_val[c][h*16+vc]*W_proj[h*16+vc]
__device__ float g_hidden[EE*128];
__device__ float g_rad[EE*128];
__device__ float g_msg[(size_t)EE*9*128];
__device__ float g_abuf[(size_t)EE*256];
__device__ float g_logits[EE*8];
__device__ float g_ex[EE*8];
__device__ float g_m[NN*8];
__device__ float g_den[NN*8];
__device__ float g_outv[NN*3];
__device__ float g_outd[NN*3];
__device__ unsigned int g_maskinfo[1];

// ------------------------- helpers -------------------------
__device__ __forceinline__ float siluf(float x) { return x / (1.f + __expf(-x)); }
__device__ __forceinline__ float sigmf(float x) { return 1.f / (1.f + __expf(-x)); }

__device__ __forceinline__ void atomicMaxFloat(float* addr, float val) {
    if (val >= 0.f) atomicMax((int*)addr, __float_as_int(val));
    else            atomicMin((unsigned int*)addr, __float_as_uint(val));
}

// ------------------------- init / mask detect -------------------------
__global__ void k_init0() {
    int tid = blockIdx.x * blockDim.x + threadIdx.x;
    if (tid < NN*3) { g_outv[tid] = 0.f; g_outd[tid] = 0.f; }
    if (tid == 0) g_maskinfo[0] = 0u;
}

__global__ void k_detect_mask(const unsigned int* __restrict__ mask) {
    int tid = blockIdx.x * blockDim.x + threadIdx.x;
    if (tid >= NN/4) return;            // read only 5000 bytes — safe for byte/int/float layouts
    unsigned int w = mask[tid];
    if (w == 0x3F800000u)      atomicOr(g_maskinfo, 2u);   // float32 1.0f
    else if (w > 1u)           atomicOr(g_maskinfo, 1u);   // packed-byte pattern
}

__global__ void k_init_mden() {
    int tid = blockIdx.x * blockDim.x + threadIdx.x;
    if (tid < NN*8) { g_m[tid] = __int_as_float(0xFF800000); g_den[tid] = 0.f; }
}

// ------------------------- tiny precompute kernels -------------------------
__global__ void k_pack_wmsg(const float* __restrict__ Wmsg) {   // [256,128] -> [128,256]
    int idx = blockIdx.x * blockDim.x + threadIdx.x;
    if (idx >= 128*256) return;
    int k = idx >> 8, c = idx & 255;
    g_WmsgC[idx] = (c < 128) ? Wmsg[k*128 + c] : Wmsg[(128 + k)*128 + (c - 128)];
}

__global__ void k_zemb(const float* __restrict__ ae, const float* __restrict__ Wrad1) {
    int z = blockIdx.x, c = threadIdx.x;    // 100 x 128
    __shared__ float aes[64];
    if (c < 64) aes[c] = ae[z*64 + c];
    __syncthreads();
    float sb = 0.f, sc = 0.f;
    #pragma unroll 8
    for (int k = 0; k < 64; k++) {
        float a = aes[k];
        sb += a * Wrad1[(128 + k)*128 + c];
        sc += a * Wrad1[(192 + k)*128 + c];
    }
    g_bz[z*128 + c] = sb;
    g_cz[z*128 + c] = sc;
}

__global__ void k_uvec(const float* __restrict__ Wval, const float* __restrict__ Wproj) {
    int h = blockIdx.x, c = threadIdx.x;    // 8 x 128
    float s = 0.f;
    #pragma unroll
    for (int vc = 0; vc < 16; vc++)
        s += Wval[c*128 + h*16 + vc] * Wproj[h*16 + vc];
    g_u[h*128 + c] = s;
}

// ------------------------- tiled fp32 GEMM: C[M,NC] = A[M,128] @ W[128,NC] -------------------------
// BM=128 BN=64 BK=16, 256 threads, 8x4 per thread. EPI: 0 = none, 1 = +bz[z_src]+cz[z_dst], silu
template<int EPI>
__global__ __launch_bounds__(256)
void k_gemm(const float* __restrict__ A, int lda,
            const float* __restrict__ W, int ldw,
            float* __restrict__ Cout, int ldc, int M,
            const int* __restrict__ srcA, const int* __restrict__ dstA,
            const int* __restrict__ zA)
{
    __shared__ float As[16][128];
    __shared__ float Ws[16][64];
    const int m0 = blockIdx.x * 128;
    const int n0 = blockIdx.y * 64;
    const int tid = threadIdx.x;
    const int arow = tid >> 2, acol = (tid & 3) * 4;
    const int wrow = tid >> 4, wcol = (tid & 15) * 4;
    const int tr = tid >> 4, tc = tid & 15;

    float acc[8][4];
    #pragma unroll
    for (int i = 0; i < 8; i++)
        #pragma unroll
        for (int j = 0; j < 4; j++) acc[i][j] = 0.f;

    for (int k0 = 0; k0 < 128; k0 += 16) {
        #pragma unroll
        for (int h = 0; h < 2; h++) {
            int row = m0 + arow + h*64;
            float4 v = make_float4(0.f, 0.f, 0.f, 0.f);
            if (row < M) v = *(const float4*)(A + (size_t)row*lda + k0 + acol);
            As[acol + 0][arow + h*64] = v.x;
            As[acol + 1][arow + h*64] = v.y;
            As[acol + 2][arow + h*64] = v.z;
            As[acol + 3][arow + h*64] = v.w;
        }
        *(float4*)&Ws[wrow][wcol] = *(const float4*)(W + (size_t)(k0 + wrow)*ldw + n0 + wcol);
        __syncthreads();
        #pragma unroll
        for (int k = 0; k < 16; k++) {
            float4 a0 = *(const float4*)&As[k][tr*8];
            float4 a1 = *(const float4*)&As[k][tr*8 + 4];
            float4 b  = *(const float4*)&Ws[k][tc*4];
            float av[8] = {a0.x, a0.y, a0.z, a0.w, a1.x, a1.y, a1.z, a1.w};
            #pragma unroll
            for (int i = 0; i < 8; i++) {
                acc[i][0] += av[i]*b.x;
                acc[i][1] += av[i]*b.y;
                acc[i][2] += av[i]*b.z;
                acc[i][3] += av[i]*b.w;
            }
        }
        __syncthreads();
    }
    #pragma unroll
    for (int i = 0; i < 8; i++) {
        int row = m0 + tr*8 + i;
        if (row >= M) break;
        float4 r = make_float4(acc[i][0], acc[i][1], acc[i][2], acc[i][3]);
        if (EPI == 1) {
            int zs = zA[srcA[row]], zd = zA[dstA[row]];
            float4 b1 = *(const float4*)(g_bz + zs*128 + n0 + tc*4);
            float4 b2 = *(const float4*)(g_cz + zd*128 + n0 + tc*4);
            r.x = siluf(r.x + b1.x + b2.x);
            r.y = siluf(r.y + b1.y + b2.y);
            r.z = siluf(r.z + b1.z + b2.z);
            r.w = siluf(r.w + b1.w + b2.w);
        }
        *(float4*)(Cout + (size_t)row*ldc + n0 + tc*4) = r;
    }
}

// ------------------------- per-edge wigner contraction + rad scale -------------------------
// msg[e,l,c] = rad[e,c] * sum_j wig[e,l,j] * (Ytop[src,j,c] + Ybot[dst,j,c])
__global__ void k_msg(const float* __restrict__ wigner,
                      const int* __restrict__ src, const int* __restrict__ dst)
{
    __shared__ float wig_s[8][81];
    const int warp = threadIdx.x >> 5, lane = threadIdx.x & 31;
    const int e = blockIdx.x * 8 + warp;
    if (e >= EE) return;
    for (int i = lane; i < 81; i += 32) wig_s[warp][i] = wigner[(size_t)e*81 + i];
    __syncwarp();
    const int s = src[e], d = dst[e];
    const float4* Ys = (const float4*)g_Y + (size_t)s*9*64 + lane;
    const float4* Yd = (const float4*)g_Y + (size_t)d*9*64 + 32 + lane;
    float4 t[9];
    #pragma unroll
    for (int j = 0; j < 9; j++) {
        float4 a = Ys[j*64], b = Yd[j*64];
        t[j] = make_float4(a.x + b.x, a.y + b.y, a.z + b.z, a.w + b.w);
    }
    float4 r4 = ((const float4*)g_rad)[(size_t)e*32 + lane];
    float4* mp = (float4*)g_msg + (size_t)e*9*32 + lane;
    #pragma unroll
    for (int l = 0; l < 9; l++) {
        float4 acc = make_float4(0.f, 0.f, 0.f, 0.f);
        #pragma unroll
        for (int j = 0; j < 9; j++) {
            float wv = wig_s[warp][l*9 + j];
            acc.x += wv*t[j].x; acc.y += wv*t[j].y; acc.z += wv*t[j].z; acc.w += wv*t[j].w;
        }
        acc.x *= r4.x; acc.y *= r4.y; acc.z *= r4.z; acc.w *= r4.w;
        mp[l*32] = acc;
    }
}

// ------------------------- logits + segment max -------------------------
__global__ void k_logits(const float* __restrict__ avec, const int* __restrict__ dst)
{
    const int warp = threadIdx.x >> 5, lane = threadIdx.x & 31;
    const int e = blockIdx.x * 8 + warp;
    if (e >= EE) return;
    const float4* ap = (const float4*)(g_abuf + (size_t)e*256) + lane*2;
    const float4* vp = (const float4*)avec + lane*2;
    float4 a0 = ap[0], a1 = ap[1];
    float4 v0 = vp[0], v1 = vp[1];
    #define LR(x) ((x) > 0.f ? (x) : 0.2f*(x))
    float p = LR(a0.x)*v0.x + LR(a0.y)*v0.y + LR(a0.z)*v0.z + LR(a0.w)*v0.w
            + LR(a1.x)*v1.x + LR(a1.y)*v1.y + LR(a1.z)*v1.z + LR(a1.w)*v1.w;
    #undef LR
    p += __shfl_xor_sync(0xffffffffu, p, 1);
    p += __shfl_xor_sync(0xffffffffu, p, 2);
    if ((lane & 3) == 0) {
        int h = lane >> 2;
        g_logits[(size_t)e*8 + h] = p;
        atomicMaxFloat(&g_m[dst[e]*8 + h], p);
    }
}

__global__ void k_expsum(const int* __restrict__ dst)
{
    int tid = blockIdx.x * blockDim.x + threadIdx.x;
    if (tid >= EE*8) return;
    int e = tid >> 3, h = tid & 7;
    int d = dst[e];
    float ex = __expf(g_logits[tid] - g_m[d*8 + h]);
    g_ex[tid] = ex;
    atomicAdd(&g_den[d*8 + h], ex);
}

// ------------------------- value path, fully folded -------------------------
__global__ void k_edge_out(const float* __restrict__ wigner,
                           const int* __restrict__ dst, float* __restrict__ outp)
{
    const int warp = threadIdx.x >> 5, lane = threadIdx.x & 31;
    const int e = blockIdx.x * 8 + warp;
    if (e >= EE) return;
    const int d = dst[e];
    float attn = 0.f;
    if (lane < 8) attn = g_ex[(size_t)e*8 + lane] / (g_den[d*8 + lane] + 1e-9f);
    float4 w = make_float4(0.f, 0.f, 0.f, 0.f);
    const float4* u4 = (const float4*)g_u;
    #pragma unroll
    for (int h = 0; h < 8; h++) {
        float ah = __shfl_sync(0xffffffffu, attn, h);
        float4 uu = u4[h*32 + lane];
        w.x += ah*uu.x; w.y += ah*uu.y; w.z += ah*uu.z; w.w += ah*uu.w;
    }
    const float4* mp = (const float4*)g_msg + (size_t)e*9*32 + lane;
    float4 m0 = mp[0];
    float4 gw = make_float4(sigmf(m0.x)*w.x, sigmf(m0.y)*w.y, sigmf(m0.z)*w.z, sigmf(m0.w)*w.w);
    float sp[9];
    sp[0] = m0.x*gw.x + m0.y*gw.y + m0.z*gw.z + m0.w*gw.w;   // silu(m0).w == m0.(sig(m0)*w)
    #pragma unroll
    for (int j = 1; j < 9; j++) {
        float4 mj = mp[j*32];
        sp[j] = mj.x*gw.x + mj.y*gw.y + mj.z*gw.z + mj.w*gw.w;
    }
    #pragma unroll
    for (int off = 16; off >= 1; off >>= 1)
        #pragma unroll
        for (int j = 0; j < 9; j++) sp[j] += __shfl_xor_sync(0xffffffffu, sp[j], off);
    if (lane < 3) {
        float v = 0.f;
        #pragma unroll
        for (int j = 0; j < 9; j++) v += wigner[(size_t)e*81 + j*9 + (lane + 1)] * sp[j];
        atomicAdd(&outp[d*3 + lane], v);
    }
}

// ------------------------- final select -------------------------
__global__ void k_final(const unsigned char* __restrict__ mask, float* __restrict__ out)
{
    int tid = blockIdx.x * blockDim.x + threadIdx.x;
    if (tid >= NN*3) return;
    int n = tid / 3;
    unsigned int info = g_maskinfo[0];
    bool mk;
    if (info & 2u)      mk = (((const float*)mask)[n] != 0.f);
    else if (info & 1u) mk = (mask[n] != 0);
    else                mk = (((const int*)mask)[n] != 0);
    out[tid] = mk ? g_outd[tid] : g_outv[tid];
}

// ------------------------- host launch -------------------------
extern "C" void kernel_launch(void* const* d_in, const int* in_sizes, int n_in,
                              void* d_out, int out_size)
{
    float *pY, *pWmsgC, *pHidden, *pRad, *pMsg, *pA, *pOutv, *pOutd;
    cudaGetSymbolAddress((void**)&pY, g_Y);
    cudaGetSymbolAddress((void**)&pWmsgC, g_WmsgC);
    cudaGetSymbolAddress((void**)&pHidden, g_hidden);
    cudaGetSymbolAddress((void**)&pRad, g_rad);
    cudaGetSymbolAddress((void**)&pMsg, g_msg);
    cudaGetSymbolAddress((void**)&pA, g_abuf);
    cudaGetSymbolAddress((void**)&pOutv, g_outv);
    cudaGetSymbolAddress((void**)&pOutd, g_outd);

    const float* node_emb  = (const float*)d_in[0];
    const float* edge_dist = (const float*)d_in[1];
    const float* wigner    = (const float*)d_in[2];
    const int *atomic_numbers, *edge_index;
    const void* mask;
    int pbase[2];
    bool dictOrder = (in_sizes[3] == NN);   // dict order: atomic_numbers at slot 3 (5000 elems)
    if (dictOrder) {
        atomic_numbers = (const int*)d_in[3];
        edge_index     = (const int*)d_in[4];
        mask           = d_in[5];
        pbase[0] = 6; pbase[1] = 14;
    } else {                                 // signature order
        pbase[0] = 3; pbase[1] = 11;
        atomic_numbers = (const int*)d_in[19];
        edge_index     = (const int*)d_in[20];
        mask           = d_in[21];
    }
    const int* src = edge_index;
    const int* dst = edge_index + EE;

    k_init0<<<(NN*3 + 255)/256, 256>>>();
    k_detect_mask<<<(NN/4 + 255)/256, 256>>>((const unsigned int*)mask);

    for (int t = 0; t < 2; t++) {
        int b = pbase[t];
        const float* ae     = (const float*)d_in[b + 0];
        const float* Wrad1  = (const float*)d_in[b + 1];
        const float* Wrad2  = (const float*)d_in[b + 2];
        const float* Wmsg   = (const float*)d_in[b + 3];
        const float* Walpha = (const float*)d_in[b + 4];
        const float* avec   = (const float*)d_in[b + 5];
        const float* Wval   = (const float*)d_in[b + 6];
        const float* Wproj  = (const float*)d_in[b + 7];

        k_pack_wmsg<<<128, 256>>>(Wmsg);
        k_zemb<<<100, 128>>>(ae, Wrad1);
        k_uvec<<<8, 128>>>(Wval, Wproj);

        // Y = node_embedding @ [Wm_top | Wm_bot]   [45000,128]@[128,256]
        k_gemm<0><<<dim3((NLROWS + 127)/128, 4), 256>>>(node_emb, 128, pWmsgC, 256, pY, 256, NLROWS,
                                                        nullptr, nullptr, nullptr);
        // hidden = silu(dist @ W1a + bz[z_src] + cz[z_dst])   [50000,128]@[128,128]
        k_gemm<1><<<dim3((EE + 127)/128, 2), 256>>>(edge_dist, 128, Wrad1, 128, pHidden, 128, EE,
                                                    src, dst, atomic_numbers);
        // rad = hidden @ W_rad2
        k_gemm<0><<<dim3((EE + 127)/128, 2), 256>>>(pHidden, 128, Wrad2, 128, pRad, 128, EE,
                                                    nullptr, nullptr, nullptr);
        // msg (wigner contraction, scaled by rad)
        k_msg<<<(EE + 7)/8, 256>>>(wigner, src, dst);
        // a = msg0 @ W_alpha   [50000,128]@[128,256], lda = 9*128
        k_gemm<0><<<dim3((EE + 127)/128, 4), 256>>>(pMsg, 1152, Walpha, 256, pA, 256, EE,
                                                    nullptr, nullptr, nullptr);
        // segment softmax
        k_init_mden<<<(NN*8 + 255)/256, 256>>>();
        k_logits<<<(EE + 7)/8, 256>>>(avec, dst);
        k_expsum<<<(EE*8 + 255)/256, 256>>>(dst);
        // folded value path + scatter
        k_edge_out<<<(EE + 7)/8, 256>>>(wigner, dst, (t == 0) ? pOutv : pOutd);
    }

    k_final<<<(NN*3 + 255)/256, 256>>>((const unsigned char*)mask, (float*)d_out);
}

// round 4
// speedup vs baseline: 1.2599x; 1.2599x over previous
#include <cuda_runtime.h>
#include <math.h>
#include <stdint.h>

#define NN    5000
#define EE    50000
#define LL    9
#define CC    128
#define NHEAD 8
#define NLROWS (NN*LL)   // 45000

// ------------------------- device scratch (static, no allocs) -------------------------
__device__ float g_Y[NLROWS*256];
__device__ float g_WmsgC[128*256];
__device__ float g_bz[100*128];
__device__ float g_cz[100*128];
__device__ float g_u[8*128];
__device__ float g_hidden[EE*128];
__device__ float g_rad[EE*128];
__device__ float g_msg[(size_t)EE*9*128];
__device__ float g_abuf[(size_t)EE*256];
__device__ float g_logits[EE*8];
__device__ float g_ex[EE*8];
__device__ float g_m[NN*8];
__device__ float g_den[NN*8];
__device__ float g_outv[NN*3];
__device__ float g_outd[NN*3];
__device__ unsigned int g_maskinfo[1];

// ------------------------- helpers -------------------------
__device__ __forceinline__ float siluf(float x) { return x / (1.f + __expf(-x)); }
__device__ __forceinline__ float sigmf(float x) { return 1.f / (1.f + __expf(-x)); }

__device__ __forceinline__ void atomicMaxFloat(float* addr, float val) {
    if (val >= 0.f) atomicMax((int*)addr, __float_as_int(val));
    else            atomicMin((unsigned int*)addr, __float_as_uint(val));
}

__device__ __forceinline__ uint32_t tf32r(float x) {
    uint32_t r;
    asm("cvt.rna.tf32.f32 %0, %1;" : "=r"(r) : "f"(x));
    return r;
}

__device__ __forceinline__ void mma_tf32(float c[4], uint32_t a0, uint32_t a1, uint32_t a2, uint32_t a3,
                                         uint32_t b0, uint32_t b1) {
    asm volatile("mma.sync.aligned.m16n8k8.row.col.f32.tf32.tf32.f32 "
                 "{%0,%1,%2,%3}, {%4,%5,%6,%7}, {%8,%9}, {%0,%1,%2,%3};"
                 : "+f"(c[0]), "+f"(c[1]), "+f"(c[2]), "+f"(c[3])
                 : "r"(a0), "r"(a1), "r"(a2), "r"(a3), "r"(b0), "r"(b1));
}

// ------------------------- init / mask detect -------------------------
__global__ void k_init0() {
    int tid = blockIdx.x * blockDim.x + threadIdx.x;
    if (tid < NN*3) { g_outv[tid] = 0.f; g_outd[tid] = 0.f; }
    if (tid == 0) g_maskinfo[0] = 0u;
}

__global__ void k_detect_mask(const unsigned int* __restrict__ mask) {
    int tid = blockIdx.x * blockDim.x + threadIdx.x;
    if (tid >= NN/4) return;
    unsigned int w = mask[tid];
    if (w == 0x3F800000u)      atomicOr(g_maskinfo, 2u);
    else if (w > 1u)           atomicOr(g_maskinfo, 1u);
}

__global__ void k_init_mden() {
    int tid = blockIdx.x * blockDim.x + threadIdx.x;
    if (tid < NN*8) { g_m[tid] = __int_as_float(0xFF800000); g_den[tid] = 0.f; }
}

// ------------------------- tiny precompute kernels -------------------------
__global__ void k_pack_wmsg(const float* __restrict__ Wmsg) {
    int idx = blockIdx.x * blockDim.x + threadIdx.x;
    if (idx >= 128*256) return;
    int k = idx >> 8, c = idx & 255;
    g_WmsgC[idx] = (c < 128) ? Wmsg[k*128 + c] : Wmsg[(128 + k)*128 + (c - 128)];
}

__global__ void k_zemb(const float* __restrict__ ae, const float* __restrict__ Wrad1) {
    int z = blockIdx.x, c = threadIdx.x;
    __shared__ float aes[64];
    if (c < 64) aes[c] = ae[z*64 + c];
    __syncthreads();
    float sb = 0.f, sc = 0.f;
    #pragma unroll 8
    for (int k = 0; k < 64; k++) {
        float a = aes[k];
        sb += a * Wrad1[(128 + k)*128 + c];
        sc += a * Wrad1[(192 + k)*128 + c];
    }
    g_bz[z*128 + c] = sb;
    g_cz[z*128 + c] = sc;
}

__global__ void k_uvec(const float* __restrict__ Wval, const float* __restrict__ Wproj) {
    int h = blockIdx.x, c = threadIdx.x;
    float s = 0.f;
    #pragma unroll
    for (int vc = 0; vc < 16; vc++)
        s += Wval[c*128 + h*16 + vc] * Wproj[h*16 + vc];
    g_u[h*128 + c] = s;
}

// ------------------------- tf32 tensor-core GEMM: C[M,N] = A[M,128] @ W[128,N] -------------------------
// BM=128, BN=128, BK=16. 256 threads = 8 warps, warp grid 4(m) x 2(n), warp tile 32x64.
// mma m16n8k8 tf32. EPI: 0 = none, 1 = silu(x + bz[z_src] + cz[z_dst]).
#define PAD 4
template<int EPI>
__global__ __launch_bounds__(256)
void k_gemm_tc(const float* __restrict__ A, int lda,
               const float* __restrict__ W, int ldw,
               float* __restrict__ Cout, int ldc, int M,
               const int* __restrict__ srcA, const int* __restrict__ dstA,
               const int* __restrict__ zA)
{
    __shared__ float As[16][128 + PAD];   // [k][m], tf32 bits
    __shared__ float Ws[16][128 + PAD];   // [k][n], tf32 bits

    const int tid  = threadIdx.x;
    const int lane = tid & 31;
    const int warp = tid >> 5;
    const int wm   = warp & 3;            // 0..3  -> m offset wm*32
    const int wn   = warp >> 2;           // 0..1  -> n offset wn*64
    const int m0   = blockIdx.x * 128;
    const int n0   = blockIdx.y * 128;

    const int g    = lane >> 2;           // group id 0..7
    const int tg   = lane & 3;            // thread-in-group 0..3

    // global-load mapping
    const int arow = tid >> 1;            // 0..127
    const int akq  = (tid & 1) * 8;       // 0 or 8
    const int wrow = tid >> 4;            // 0..15
    const int wcol = (tid & 15) * 8;      // 0..120

    float acc[2][8][4];
    #pragma unroll
    for (int mi = 0; mi < 2; mi++)
        #pragma unroll
        for (int ni = 0; ni < 8; ni++)
            #pragma unroll
            for (int r = 0; r < 4; r++) acc[mi][ni][r] = 0.f;

    for (int k0 = 0; k0 < 128; k0 += 16) {
        // A tile: 128 rows x 16 k, transposed into As[k][m]
        {
            int row = m0 + arow;
            float4 v0 = make_float4(0.f,0.f,0.f,0.f), v1 = v0;
            if (row < M) {
                const float* ap = A + (size_t)row*lda + k0 + akq;
                v0 = *(const float4*)ap;
                v1 = *(const float4*)(ap + 4);
            }
            As[akq + 0][arow] = __uint_as_float(tf32r(v0.x));
            As[akq + 1][arow] = __uint_as_float(tf32r(v0.y));
            As[akq + 2][arow] = __uint_as_float(tf32r(v0.z));
            As[akq + 3][arow] = __uint_as_float(tf32r(v0.w));
            As[akq + 4][arow] = __uint_as_float(tf32r(v1.x));
            As[akq + 5][arow] = __uint_as_float(tf32r(v1.y));
            As[akq + 6][arow] = __uint_as_float(tf32r(v1.z));
            As[akq + 7][arow] = __uint_as_float(tf32r(v1.w));
        }
        // W tile: 16 k x 128 n
        {
            const float* wp = W + (size_t)(k0 + wrow)*ldw + n0 + wcol;
            float4 v0 = *(const float4*)wp;
            float4 v1 = *(const float4*)(wp + 4);
            Ws[wrow][wcol + 0] = __uint_as_float(tf32r(v0.x));
            Ws[wrow][wcol + 1] = __uint_as_float(tf32r(v0.y));
            Ws[wrow][wcol + 2] = __uint_as_float(tf32r(v0.z));
            Ws[wrow][wcol + 3] = __uint_as_float(tf32r(v0.w));
            Ws[wrow][wcol + 4] = __uint_as_float(tf32r(v1.x));
            Ws[wrow][wcol + 5] = __uint_as_float(tf32r(v1.y));
            Ws[wrow][wcol + 6] = __uint_as_float(tf32r(v1.z));
            Ws[wrow][wcol + 7] = __uint_as_float(tf32r(v1.w));
        }
        __syncthreads();

        #pragma unroll
        for (int ki = 0; ki < 16; ki += 8) {
            uint32_t afrag[2][4];
            #pragma unroll
            for (int mi = 0; mi < 2; mi++) {
                int m = wm*32 + mi*16 + g;
                afrag[mi][0] = __float_as_uint(As[ki + tg    ][m    ]);
                afrag[mi][1] = __float_as_uint(As[ki + tg    ][m + 8]);
                afrag[mi][2] = __float_as_uint(As[ki + tg + 4][m    ]);
                afrag[mi][3] = __float_as_uint(As[ki + tg + 4][m + 8]);
            }
            #pragma unroll
            for (int ni = 0; ni < 8; ni++) {
                int n = wn*64 + ni*8 + g;
                uint32_t b0 = __float_as_uint(Ws[ki + tg    ][n]);
                uint32_t b1 = __float_as_uint(Ws[ki + tg + 4][n]);
                mma_tf32(acc[0][ni], afrag[0][0], afrag[0][1], afrag[0][2], afrag[0][3], b0, b1);
                mma_tf32(acc[1][ni], afrag[1][0], afrag[1][1], afrag[1][2], afrag[1][3], b0, b1);
            }
        }
        __syncthreads();
    }

    // epilogue
    #pragma unroll
    for (int mi = 0; mi < 2; mi++) {
        #pragma unroll
        for (int r = 0; r < 2; r++) {
            int row = m0 + wm*32 + mi*16 + g + r*8;
            if (row >= M) continue;
            int colbase = n0 + wn*64 + 2*tg;
            if (EPI == 1) {
                int zs = zA[srcA[row]], zd = zA[dstA[row]];
                #pragma unroll
                for (int ni = 0; ni < 8; ni++) {
                    int col = colbase + ni*8;
                    float c0 = acc[mi][ni][r*2 + 0];
                    float c1 = acc[mi][ni][r*2 + 1];
                    c0 = siluf(c0 + g_bz[zs*128 + col]     + g_cz[zd*128 + col]);
                    c1 = siluf(c1 + g_bz[zs*128 + col + 1] + g_cz[zd*128 + col + 1]);
                    *(float2*)(Cout + (size_t)row*ldc + col) = make_float2(c0, c1);
                }
            } else {
                #pragma unroll
                for (int ni = 0; ni < 8; ni++) {
                    int col = colbase + ni*8;
                    *(float2*)(Cout + (size_t)row*ldc + col) =
                        make_float2(acc[mi][ni][r*2 + 0], acc[mi][ni][r*2 + 1]);
                }
            }
        }
    }
}

// ------------------------- per-edge wigner contraction + rad scale -------------------------
__global__ void k_msg(const float* __restrict__ wigner,
                      const int* __restrict__ src, const int* __restrict__ dst)
{
    __shared__ float wig_s[8][81];
    const int warp = threadIdx.x >> 5, lane = threadIdx.x & 31;
    const int e = blockIdx.x * 8 + warp;
    if (e >= EE) return;
    for (int i = lane; i < 81; i += 32) wig_s[warp][i] = wigner[(size_t)e*81 + i];
    __syncwarp();
    const int s = src[e], d = dst[e];
    const float4* Ys = (const float4*)g_Y + (size_t)s*9*64 + lane;
    const float4* Yd = (const float4*)g_Y + (size_t)d*9*64 + 32 + lane;
    float4 t[9];
    #pragma unroll
    for (int j = 0; j < 9; j++) {
        float4 a = Ys[j*64], b = Yd[j*64];
        t[j] = make_float4(a.x + b.x, a.y + b.y, a.z + b.z, a.w + b.w);
    }
    float4 r4 = ((const float4*)g_rad)[(size_t)e*32 + lane];
    float4* mp = (float4*)g_msg + (size_t)e*9*32 + lane;
    #pragma unroll
    for (int l = 0; l < 9; l++) {
        float4 acc = make_float4(0.f, 0.f, 0.f, 0.f);
        #pragma unroll
        for (int j = 0; j < 9; j++) {
            float wv = wig_s[warp][l*9 + j];
            acc.x += wv*t[j].x; acc.y += wv*t[j].y; acc.z += wv*t[j].z; acc.w += wv*t[j].w;
        }
        acc.x *= r4.x; acc.y *= r4.y; acc.z *= r4.z; acc.w *= r4.w;
        mp[l*32] = acc;
    }
}

// ------------------------- logits + segment max -------------------------
__global__ void k_logits(const float* __restrict__ avec, const int* __restrict__ dst)
{
    const int warp = threadIdx.x >> 5, lane = threadIdx.x & 31;
    const int e = blockIdx.x * 8 + warp;
    if (e >= EE) return;
    const float4* ap = (const float4*)(g_abuf + (size_t)e*256) + lane*2;
    const float4* vp = (const float4*)avec + lane*2;
    float4 a0 = ap[0], a1 = ap[1];
    float4 v0 = vp[0], v1 = vp[1];
    #define LR(x) ((x) > 0.f ? (x) : 0.2f*(x))
    float p = LR(a0.x)*v0.x + LR(a0.y)*v0.y + LR(a0.z)*v0.z + LR(a0.w)*v0.w
            + LR(a1.x)*v1.x + LR(a1.y)*v1.y + LR(a1.z)*v1.z + LR(a1.w)*v1.w;
    #undef LR
    p += __shfl_xor_sync(0xffffffffu, p, 1);
    p += __shfl_xor_sync(0xffffffffu, p, 2);
    if ((lane & 3) == 0) {
        int h = lane >> 2;
        g_logits[(size_t)e*8 + h] = p;
        atomicMaxFloat(&g_m[dst[e]*8 + h], p);
    }
}

__global__ void k_expsum(const int* __restrict__ dst)
{
    int tid = blockIdx.x * blockDim.x + threadIdx.x;
    if (tid >= EE*8) return;
    int e = tid >> 3, h = tid & 7;
    int d = dst[e];
    float ex = __expf(g_logits[tid] - g_m[d*8 + h]);
    g_ex[tid] = ex;
    atomicAdd(&g_den[d*8 + h], ex);
}

// ------------------------- value path, fully folded -------------------------
__global__ void k_edge_out(const float* __restrict__ wigner,
                           const int* __restrict__ dst, float* __restrict__ outp)
{
    const int warp = threadIdx.x >> 5, lane = threadIdx.x & 31;
    const int e = blockIdx.x * 8 + warp;
    if (e >= EE) return;
    const int d = dst[e];
    float attn = 0.f;
    if (lane < 8) attn = g_ex[(size_t)e*8 + lane] / (g_den[d*8 + lane] + 1e-9f);
    float4 w = make_float4(0.f, 0.f, 0.f, 0.f);
    const float4* u4 = (const float4*)g_u;
    #pragma unroll
    for (int h = 0; h < 8; h++) {
        float ah = __shfl_sync(0xffffffffu, attn, h);
        float4 uu = u4[h*32 + lane];
        w.x += ah*uu.x; w.y += ah*uu.y; w.z += ah*uu.z; w.w += ah*uu.w;
    }
    const float4* mp = (const float4*)g_msg + (size_t)e*9*32 + lane;
    float4 m0 = mp[0];
    float4 gw = make_float4(sigmf(m0.x)*w.x, sigmf(m0.y)*w.y, sigmf(m0.z)*w.z, sigmf(m0.w)*w.w);
    float sp[9];
    sp[0] = m0.x*gw.x + m0.y*gw.y + m0.z*gw.z + m0.w*gw.w;
    #pragma unroll
    for (int j = 1; j < 9; j++) {
        float4 mj = mp[j*32];
        sp[j] = mj.x*gw.x + mj.y*gw.y + mj.z*gw.z + mj.w*gw.w;
    }
    #pragma unroll
    for (int off = 16; off >= 1; off >>= 1)
        #pragma unroll
        for (int j = 0; j < 9; j++) sp[j] += __shfl_xor_sync(0xffffffffu, sp[j], off);
    if (lane < 3) {
        float v = 0.f;
        #pragma unroll
        for (int j = 0; j < 9; j++) v += wigner[(size_t)e*81 + j*9 + (lane + 1)] * sp[j];
        atomicAdd(&outp[d*3 + lane], v);
    }
}

// ------------------------- final select -------------------------
__global__ void k_final(const unsigned char* __restrict__ mask, float* __restrict__ out)
{
    int tid = blockIdx.x * blockDim.x + threadIdx.x;
    if (tid >= NN*3) return;
    int n = tid / 3;
    unsigned int info = g_maskinfo[0];
    bool mk;
    if (info & 2u)      mk = (((const float*)mask)[n] != 0.f);
    else if (info & 1u) mk = (mask[n] != 0);
    else                mk = (((const int*)mask)[n] != 0);
    out[tid] = mk ? g_outd[tid] : g_outv[tid];
}

// ------------------------- host launch -------------------------
extern "C" void kernel_launch(void* const* d_in, const int* in_sizes, int n_in,
                              void* d_out, int out_size)
{
    float *pY, *pWmsgC, *pHidden, *pRad, *pMsg, *pA, *pOutv, *pOutd;
    cudaGetSymbolAddress((void**)&pY, g_Y);
    cudaGetSymbolAddress((void**)&pWmsgC, g_WmsgC);
    cudaGetSymbolAddress((void**)&pHidden, g_hidden);
    cudaGetSymbolAddress((void**)&pRad, g_rad);
    cudaGetSymbolAddress((void**)&pMsg, g_msg);
    cudaGetSymbolAddress((void**)&pA, g_abuf);
    cudaGetSymbolAddress((void**)&pOutv, g_outv);
    cudaGetSymbolAddress((void**)&pOutd, g_outd);

    const float* node_emb  = (const float*)d_in[0];
    const float* edge_dist = (const float*)d_in[1];
    const float* wigner    = (const float*)d_in[2];
    const int *atomic_numbers, *edge_index;
    const void* mask;
    int pbase[2];
    bool dictOrder = (in_sizes[3] == NN);
    if (dictOrder) {
        atomic_numbers = (const int*)d_in[3];
        edge_index     = (const int*)d_in[4];
        mask           = d_in[5];
        pbase[0] = 6; pbase[1] = 14;
    } else {
        pbase[0] = 3; pbase[1] = 11;
        atomic_numbers = (const int*)d_in[19];
        edge_index     = (const int*)d_in[20];
        mask           = d_in[21];
    }
    const int* src = edge_index;
    const int* dst = edge_index + EE;

    k_init0<<<(NN*3 + 255)/256, 256>>>();
    k_detect_mask<<<(NN/4 + 255)/256, 256>>>((const unsigned int*)mask);

    for (int t = 0; t < 2; t++) {
        int b = pbase[t];
        const float* ae     = (const float*)d_in[b + 0];
        const float* Wrad1  = (const float*)d_in[b + 1];
        const float* Wrad2  = (const float*)d_in[b + 2];
        const float* Wmsg   = (const float*)d_in[b + 3];
        const float* Walpha = (const float*)d_in[b + 4];
        const float* avec   = (const float*)d_in[b + 5];
        const float* Wval   = (const float*)d_in[b + 6];
        const float* Wproj  = (const float*)d_in[b + 7];

        k_pack_wmsg<<<128, 256>>>(Wmsg);
        k_zemb<<<100, 128>>>(ae, Wrad1);
        k_uvec<<<8, 128>>>(Wval, Wproj);

        // Y = node_embedding @ [Wm_top | Wm_bot]   [45000,128]@[128,256]
        k_gemm_tc<0><<<dim3((NLROWS + 127)/128, 2), 256>>>(node_emb, 128, pWmsgC, 256, pY, 256, NLROWS,
                                                           nullptr, nullptr, nullptr);
        // hidden = silu(dist @ W1a + bz[z_src] + cz[z_dst])   [50000,128]@[128,128]
        k_gemm_tc<1><<<dim3((EE + 127)/128, 1), 256>>>(edge_dist, 128, Wrad1, 128, pHidden, 128, EE,
                                                       src, dst, atomic_numbers);
        // rad = hidden @ W_rad2
        k_gemm_tc<0><<<dim3((EE + 127)/128, 1), 256>>>(pHidden, 128, Wrad2, 128, pRad, 128, EE,
                                                       nullptr, nullptr, nullptr);
        // msg (wigner contraction, scaled by rad)
        k_msg<<<(EE + 7)/8, 256>>>(wigner, src, dst);
        // a = msg0 @ W_alpha   [50000,128]@[128,256], lda = 9*128
        k_gemm_tc<0><<<dim3((EE + 127)/128, 2), 256>>>(pMsg, 1152, Walpha, 256, pA, 256, EE,
                                                       nullptr, nullptr, nullptr);
        // segment softmax
        k_init_mden<<<(NN*8 + 255)/256, 256>>>();
        k_logits<<<(EE + 7)/8, 256>>>(avec, dst);
        k_expsum<<<(EE*8 + 255)/256, 256>>>(dst);
        // folded value path + scatter
        k_edge_out<<<(EE + 7)/8, 256>>>(wigner, dst, (t == 0) ? pOutv : pOutd);
    }

    k_final<<<(NN*3 + 255)/256, 256>>>((const unsigned char*)mask, (float*)d_out);
}